// round 9
// baseline (speedup 1.0000x reference)
#include <cuda_runtime.h>

#define HID   100
#define G4    400      // 4 * HID
#define SEQ   8192
#define NCLS  20
#define TPB   16       // timesteps per block in xproj kernel

// 13.1 MB scratch for x_proj (allowed: __device__ global, no allocation)
__device__ float g_xproj[SEQ * G4];

// ---------- packed f32x2 helpers (sm_100+) ----------
__device__ __forceinline__ unsigned long long ffma2(unsigned long long a,
                                                    unsigned long long b,
                                                    unsigned long long c) {
    unsigned long long d;
    asm("fma.rn.f32x2 %0, %1, %2, %3;" : "=l"(d) : "l"(a), "l"(b), "l"(c));
    return d;
}
__device__ __forceinline__ unsigned long long fadd2(unsigned long long a,
                                                    unsigned long long b) {
    unsigned long long d;
    asm("add.rn.f32x2 %0, %1, %2;" : "=l"(d) : "l"(a), "l"(b));
    return d;
}
__device__ __forceinline__ unsigned long long pack2(float x, float y) {
    unsigned long long v;
    asm("mov.b64 %0, {%1, %2};" : "=l"(v) : "f"(x), "f"(y));
    return v;
}
__device__ __forceinline__ float2 unpack2(unsigned long long v) {
    float2 f;
    asm("mov.b64 {%0, %1}, %2;" : "=f"(f.x), "=f"(f.y) : "l"(v));
    return f;
}

__device__ __forceinline__ float sigmoid_f(float x) {
    return 1.0f / (1.0f + __expf(-x));
}
__device__ __forceinline__ float tanh_f(float x) {
    return 2.0f / (1.0f + __expf(-2.0f * x)) - 1.0f;
}

// ---------------------------------------------------------------------------
// Kernel 1: x_proj[t][j] = emb[seq[t]] . W_ih[j] + b_ih[j] + b_hh[j]
// ---------------------------------------------------------------------------
__global__ __launch_bounds__(416, 1)
void xproj_kernel(const int* __restrict__ seq,
                  const float* __restrict__ emb,
                  const float* __restrict__ Wih,
                  const float* __restrict__ bih,
                  const float* __restrict__ bhh)
{
    __shared__ __align__(16) float se[TPB][HID];
    const int t0  = blockIdx.x * TPB;
    const int tid = threadIdx.x;

    for (int idx = tid; idx < TPB * HID; idx += blockDim.x) {
        int t = idx / HID;
        int k = idx - t * HID;
        se[t][k] = emb[(long long)seq[t0 + t] * HID + k];
    }
    __syncthreads();

    if (tid < G4) {
        float4 w[25];
        const float4* wr = reinterpret_cast<const float4*>(Wih + tid * HID);
#pragma unroll
        for (int q = 0; q < 25; q++) w[q] = wr[q];
        const float bias = bih[tid] + bhh[tid];

        for (int t = 0; t < TPB; t++) {
            const float4* hv = reinterpret_cast<const float4*>(se[t]);
            float a0 = 0.f, a1 = 0.f, a2 = 0.f, a3 = 0.f;
#pragma unroll
            for (int q = 0; q < 25; q++) {
                float4 h4 = hv[q];
                a0 = fmaf(w[q].x, h4.x, a0);
                a1 = fmaf(w[q].y, h4.y, a1);
                a2 = fmaf(w[q].z, h4.z, a2);
                a3 = fmaf(w[q].w, h4.w, a3);
            }
            g_xproj[(t0 + t) * G4 + tid] = (a0 + a1) + (a2 + a3) + bias;
        }
    }
}

// ---------------------------------------------------------------------------
// Kernel 2: persistent single-block LSTM recurrence + final FC.
// 800 threads = 25 full warps. Thread pair (2r, 2r+1) owns gate row r:
//   half = tid&1 selects K-half [half*50, half*50+50) of W_hh row r,
//   held as 25 packed f32x2 registers. Partial sums combined via shfl_xor(1).
// sh_h is stored in two 16B-aligned banks (offsets 0 and 64 floats) so each
// half reads LDS.128-aligned vectors.
// Even threads < 200 own c[j] and perform the cell update.
// g_xproj is software-pipelined one full step ahead (xv_next).
// ---------------------------------------------------------------------------
__global__ __launch_bounds__(800, 1)
void lstm_kernel(const float* __restrict__ Whh,
                 const float* __restrict__ fcw,
                 const float* __restrict__ fcb,
                 float* __restrict__ out)
{
    __shared__ __align__(16) float sh_h[128];   // half0 @ [0..49], half1 @ [64..113]
    __shared__ float sh_act[G4];

    const int tid  = threadIdx.x;
    const int row  = tid >> 1;      // gate row 0..399
    const int half = tid & 1;       // K-half

    // preload this thread's 50 weights as 25 packed f32x2
    unsigned long long w[25];
    {
        const float2* wr = reinterpret_cast<const float2*>(Whh + row * HID + half * 50);
#pragma unroll
        for (int q = 0; q < 25; q++) {
            float2 v = wr[q];
            w[q] = pack2(v.x, v.y);
        }
    }
    if (tid < 128) sh_h[tid] = 0.0f;
    float c = 0.0f;
    const bool is_g = (row >= 2 * HID) && (row < 3 * HID);  // tanh gate
    __syncthreads();

    const float* xp = g_xproj + row;

    float xv = xp[0];                 // prologue: step-0 input projection
    for (int t = 0; t < SEQ; t++) {
        // prefetch next step's xp a full step (~>=700 cyc) ahead
        float xv_next = (t + 1 < SEQ) ? xp[(t + 1) * G4] : 0.0f;

        const char* hb = reinterpret_cast<const char*>(sh_h) + half * 256;
        unsigned long long a0 = 0ull, a1 = 0ull;
#pragma unroll
        for (int q = 0; q < 12; q++) {
            ulonglong2 hv = reinterpret_cast<const ulonglong2*>(hb)[q];  // LDS.128
            a0 = ffma2(w[2 * q],     hv.x, a0);
            a1 = ffma2(w[2 * q + 1], hv.y, a1);
        }
        {   // last 2 of the 50 elements
            unsigned long long hv2 = reinterpret_cast<const unsigned long long*>(hb)[24];
            a0 = ffma2(w[24], hv2, a0);
        }
        float2 f = unpack2(fadd2(a0, a1));
        float sum = f.x + f.y;
        sum += __shfl_xor_sync(0xFFFFFFFFu, sum, 1);   // combine K-halves (same warp)
        float gate = sum + xv;

        // PyTorch gate order: i(0..99) f(100..199) g(200..299) o(300..399)
        float act = is_g ? tanh_f(gate) : sigmoid_f(gate);
        sh_act[row] = act;   // both lanes write the same value (benign)
        __syncthreads();

        if (tid < 200 && half == 0) {   // j = row in 0..99
            float iv = sh_act[row];
            float fv = sh_act[HID + row];
            float gv = sh_act[2 * HID + row];
            float ov = sh_act[3 * HID + row];
            c = fmaf(fv, c, iv * gv);
            float hv = ov * tanh_f(c);
            sh_h[row + (row >= 50 ? 14 : 0)] = hv;   // padded layout
        }
        __syncthreads();

        xv = xv_next;
    }

    // final FC: out[n] = h_last . fc_w[n] + fc_b[n]  (handle padded sh_h layout)
    if (tid < NCLS) {
        float s = fcb[tid];
        const float* wr = fcw + tid * HID;
#pragma unroll 4
        for (int k = 0; k < HID; k++) {
            float hk = sh_h[k + (k >= 50 ? 14 : 0)];
            s = fmaf(wr[k], hk, s);
        }
        out[tid] = s;
    }
}

// ---------------------------------------------------------------------------
extern "C" void kernel_launch(void* const* d_in, const int* in_sizes, int n_in,
                              void* d_out, int out_size)
{
    const int*   seq = (const int*)  d_in[0];
    const float* emb = (const float*)d_in[1];
    const float* Wih = (const float*)d_in[2];
    const float* Whh = (const float*)d_in[3];
    const float* bih = (const float*)d_in[4];
    const float* bhh = (const float*)d_in[5];
    const float* fcw = (const float*)d_in[6];
    const float* fcb = (const float*)d_in[7];

    xproj_kernel<<<SEQ / TPB, 416>>>(seq, emb, Wih, bih, bhh);
    lstm_kernel<<<1, 800>>>(Whh, fcw, fcb, (float*)d_out);
}

// round 13
// speedup vs baseline: 1.7698x; 1.7698x over previous
#include <cuda_runtime.h>

#define HID   100
#define G4    400      // 4 * HID
#define SEQ   8192
#define NCLS  20
#define TPB   16       // timesteps per block in xproj kernel

// 13.1 MB scratch for x_proj, layout [t][j][gate] (float4 per j)
__device__ float g_xproj[SEQ * G4];

// ---------- packed f32x2 helpers (sm_100+) ----------
__device__ __forceinline__ unsigned long long ffma2(unsigned long long a,
                                                    unsigned long long b,
                                                    unsigned long long c) {
    unsigned long long d;
    asm("fma.rn.f32x2 %0, %1, %2, %3;" : "=l"(d) : "l"(a), "l"(b), "l"(c));
    return d;
}
__device__ __forceinline__ unsigned long long pack2(float x, float y) {
    unsigned long long v;
    asm("mov.b64 %0, {%1, %2};" : "=l"(v) : "f"(x), "f"(y));
    return v;
}
__device__ __forceinline__ float2 unpack2(unsigned long long v) {
    float2 f;
    asm("mov.b64 {%0, %1}, %2;" : "=f"(f.x), "=f"(f.y) : "l"(v));
    return f;
}

__device__ __forceinline__ float sigmoid_f(float x) {
    return __fdividef(1.0f, 1.0f + __expf(-x));
}
__device__ __forceinline__ float tanh_f(float x) {
    return __fdividef(2.0f, 1.0f + __expf(-2.0f * x)) - 1.0f;
}

// ---------------------------------------------------------------------------
// Kernel 1: x_proj -> g_xproj[t][j][gate] = emb[seq[t]] . W_ih[row] + biases
// (row = gate*100 + j; output interleaved so the LSTM reads one float4 per j)
// ---------------------------------------------------------------------------
__global__ __launch_bounds__(416, 1)
void xproj_kernel(const int* __restrict__ seq,
                  const float* __restrict__ emb,
                  const float* __restrict__ Wih,
                  const float* __restrict__ bih,
                  const float* __restrict__ bhh)
{
    __shared__ __align__(16) float se[TPB][HID];
    const int t0  = blockIdx.x * TPB;
    const int tid = threadIdx.x;

    for (int idx = tid; idx < TPB * HID; idx += blockDim.x) {
        int t = idx / HID;
        int k = idx - t * HID;
        se[t][k] = emb[(long long)seq[t0 + t] * HID + k];
    }
    __syncthreads();

    if (tid < G4) {
        const int j    = tid % 100;
        const int gate = tid / 100;
        float4 w[25];
        const float4* wr = reinterpret_cast<const float4*>(Wih + tid * HID);
#pragma unroll
        for (int q = 0; q < 25; q++) w[q] = wr[q];
        const float bias = bih[tid] + bhh[tid];

        for (int t = 0; t < TPB; t++) {
            const float4* hv = reinterpret_cast<const float4*>(se[t]);
            float a0 = 0.f, a1 = 0.f, a2 = 0.f, a3 = 0.f;
#pragma unroll
            for (int q = 0; q < 25; q++) {
                float4 h4 = hv[q];
                a0 = fmaf(w[q].x, h4.x, a0);
                a1 = fmaf(w[q].y, h4.y, a1);
                a2 = fmaf(w[q].z, h4.z, a2);
                a3 = fmaf(w[q].w, h4.w, a3);
            }
            g_xproj[(t0 + t) * G4 + j * 4 + gate] = (a0 + a1) + (a2 + a3) + bias;
        }
    }
}

// ---------------------------------------------------------------------------
// Kernel 2: persistent single-block LSTM recurrence + final FC.
// 416 threads = 13 full warps. Thread quad (j = tid>>2, kq = tid&3) computes
// ALL FOUR gate rows of j over k-quarter [25kq, 25kq+25):
//   - LDS traffic minimized: one h-chunk read feeds 4 gate rows
//   - quad butterfly (shfl_xor 1,2) -> every lane holds all 4 full gate sums
//   - activations + c[j] update done redundantly in all 4 lanes (bit-identical)
//   - ping-pong h buffers -> ONE __syncthreads per step
// h chunks padded to stride 36 floats => 4 kq-chunks hit disjoint bank groups.
// Threads 400..415 run with j clamped to 99 (keeps warps uniform), never store.
// ---------------------------------------------------------------------------
__global__ __launch_bounds__(416, 1)
void lstm_kernel(const float* __restrict__ Whh,
                 const float* __restrict__ fcw,
                 const float* __restrict__ fcb,
                 float* __restrict__ out)
{
    __shared__ __align__(16) float sh_h[2][4 * 36];   // ping-pong, chunk stride 36

    const int tid = threadIdx.x;
    int jq = tid >> 2;
    const int j   = (jq > 99) ? 99 : jq;   // clamp for threads 400..415
    const int kq  = tid & 3;
    const bool writer = (tid < 400) && (kq == 0);

    // preload W_hh rows {j, 100+j, 200+j, 300+j}, cols [25kq, 25kq+25)
    // as 12 packed f32x2 + 1 scalar per row  (~100 weight regs)
    unsigned long long w2[4][12];
    float wlast[4];
#pragma unroll
    for (int g = 0; g < 4; g++) {
        const float* wr = Whh + (g * 100 + j) * HID + kq * 25;
#pragma unroll
        for (int q = 0; q < 12; q++) w2[g][q] = pack2(wr[2 * q], wr[2 * q + 1]);
        wlast[g] = wr[24];
    }
    if (tid < 144) { sh_h[0][tid] = 0.0f; sh_h[1][tid] = 0.0f; }
    float c = 0.0f;
    __syncthreads();

    // xp float4 pointer for this j; stride 100 float4 per timestep
    const float4* xp4 = reinterpret_cast<const float4*>(g_xproj) + j;

    float4 xv = xp4[0];
    for (int t = 0; t < SEQ; t++) {
        float4 xv_next = (t + 1 < SEQ) ? xp4[(t + 1) * 100] : make_float4(0, 0, 0, 0);

        const float* hc = sh_h[t & 1] + kq * 36;   // 144B-aligned chunk
        unsigned long long a0 = 0ull, a1 = 0ull, a2 = 0ull, a3 = 0ull;
#pragma unroll
        for (int q2 = 0; q2 < 6; q2++) {
            ulonglong2 hv = reinterpret_cast<const ulonglong2*>(hc)[q2];  // LDS.128
            a0 = ffma2(w2[0][2 * q2], hv.x, a0);
            a1 = ffma2(w2[1][2 * q2], hv.x, a1);
            a2 = ffma2(w2[2][2 * q2], hv.x, a2);
            a3 = ffma2(w2[3][2 * q2], hv.x, a3);
            a0 = ffma2(w2[0][2 * q2 + 1], hv.y, a0);
            a1 = ffma2(w2[1][2 * q2 + 1], hv.y, a1);
            a2 = ffma2(w2[2][2 * q2 + 1], hv.y, a2);
            a3 = ffma2(w2[3][2 * q2 + 1], hv.y, a3);
        }
        const float hlast = hc[24];   // 25th element of the chunk
        float s0, s1, s2, s3;
        { float2 p = unpack2(a0); s0 = fmaf(wlast[0], hlast, p.x + p.y); }
        { float2 p = unpack2(a1); s1 = fmaf(wlast[1], hlast, p.x + p.y); }
        { float2 p = unpack2(a2); s2 = fmaf(wlast[2], hlast, p.x + p.y); }
        { float2 p = unpack2(a3); s3 = fmaf(wlast[3], hlast, p.x + p.y); }

        // quad butterfly: all 4 lanes end with identical full sums
        s0 += __shfl_xor_sync(0xFFFFFFFFu, s0, 1);
        s1 += __shfl_xor_sync(0xFFFFFFFFu, s1, 1);
        s2 += __shfl_xor_sync(0xFFFFFFFFu, s2, 1);
        s3 += __shfl_xor_sync(0xFFFFFFFFu, s3, 1);
        s0 += __shfl_xor_sync(0xFFFFFFFFu, s0, 2);
        s1 += __shfl_xor_sync(0xFFFFFFFFu, s1, 2);
        s2 += __shfl_xor_sync(0xFFFFFFFFu, s2, 2);
        s3 += __shfl_xor_sync(0xFFFFFFFFu, s3, 2);

        // gates (PyTorch order i,f,g,o), redundantly in all quad lanes
        float iv = sigmoid_f(s0 + xv.x);
        float fv = sigmoid_f(s1 + xv.y);
        float gv = tanh_f   (s2 + xv.z);
        float ov = sigmoid_f(s3 + xv.w);
        c = fmaf(fv, c, iv * gv);
        float hj = ov * tanh_f(c);

        if (writer)
            sh_h[(t & 1) ^ 1][(j / 25) * 36 + (j % 25)] = hj;
        __syncthreads();   // single barrier: publishes new h, retires old reads

        xv = xv_next;
    }

    // final FC: h_last lives in sh_h[SEQ & 1] == sh_h[0] (padded layout)
    if (tid < NCLS) {
        const float* fin = sh_h[SEQ & 1];
        float s = fcb[tid];
        const float* wr = fcw + tid * HID;
#pragma unroll 4
        for (int k = 0; k < HID; k++) {
            float hk = fin[(k / 25) * 36 + (k % 25)];
            s = fmaf(wr[k], hk, s);
        }
        out[tid] = s;
    }
}

// ---------------------------------------------------------------------------
extern "C" void kernel_launch(void* const* d_in, const int* in_sizes, int n_in,
                              void* d_out, int out_size)
{
    const int*   seq = (const int*)  d_in[0];
    const float* emb = (const float*)d_in[1];
    const float* Wih = (const float*)d_in[2];
    const float* Whh = (const float*)d_in[3];
    const float* bih = (const float*)d_in[4];
    const float* bhh = (const float*)d_in[5];
    const float* fcw = (const float*)d_in[6];
    const float* fcb = (const float*)d_in[7];

    xproj_kernel<<<SEQ / TPB, 416>>>(seq, emb, Wih, bih, bhh);
    lstm_kernel<<<1, 416>>>(Whh, fcw, fcb, (float*)d_out);
}